// round 9
// baseline (speedup 1.0000x reference)
#include <cuda_runtime.h>
#include <math.h>

#define BB 32
#define SS 1024
#define II 512
#define HH 512
#define GG 2048   // 4*H

typedef unsigned long long u64;

// ---------------- device scratch ----------------
__device__ float g_xt[(size_t)SS * 256 * 64];   // x transposed: [t][kpair][b][2], 64MB
__device__ float g_hb[2][HH * BB];              // h ping-pong: [kquad][b][4]
__device__ unsigned g_sub[8 * 32];              // barrier: 8 sub-counters (16 CTAs each)
__device__ unsigned g_top[32];                  // top counter (8 subs)
__device__ unsigned g_mail[128 * 32];           // per-CTA mailbox: latest finished window

__device__ __forceinline__ unsigned ld_acq(const unsigned* p) {
    unsigned v;
    asm volatile("ld.acquire.gpu.u32 %0, [%1];" : "=r"(v) : "l"(p));
    return v;
}
__device__ __forceinline__ void st_rel(unsigned* p, unsigned v) {
    asm volatile("st.release.gpu.u32 [%0], %1;" :: "l"(p), "r"(v));
}
__device__ __forceinline__ u64 fma2(u64 a, u64 b, u64 c) {
    u64 d;
    asm("fma.rn.f32x2 %0, %1, %2, %3;" : "=l"(d) : "l"(a), "l"(b), "l"(c));
    return d;
}
__device__ __forceinline__ u64 add2(u64 a, u64 b) {
    u64 d;
    asm("add.rn.f32x2 %0, %1, %2;" : "=l"(d) : "l"(a), "l"(b));
    return d;
}
__device__ __forceinline__ float2 unpack2(u64 v) {
    unsigned lo, hi;
    asm("mov.b64 {%0, %1}, %2;" : "=r"(lo), "=r"(hi) : "l"(v));
    return make_float2(__uint_as_float(lo), __uint_as_float(hi));
}
__device__ __forceinline__ u64 ldcg_u64(const u64* p) {
    u64 v;
    asm volatile("ld.global.cg.u64 %0, [%1];" : "=l"(v) : "l"(p));
    return v;
}
__device__ __forceinline__ ulonglong2 ldcg_v2u64(const void* p) {
    ulonglong2 v;
    asm volatile("ld.global.cg.v2.u64 {%0, %1}, [%2];"
                 : "=l"(v.x), "=l"(v.y) : "l"(p));
    return v;
}
__device__ __forceinline__ void stcg_v4f32(float* p, float a, float b, float c, float d) {
    asm volatile("st.global.cg.v4.f32 [%0], {%1, %2, %3, %4};"
                 :: "l"(p), "f"(a), "f"(b), "f"(c), "f"(d));
}
__device__ __forceinline__ float sigmoid_fast(float x) {
    return __fdividef(1.f, 1.f + __expf(-x));
}
__device__ __forceinline__ float tanh_fast(float x) {
    float e2 = __expf(2.f * fabsf(x));
    float r  = 1.f - __fdividef(2.f, e2 + 1.f);
    return copysignf(r, x);
}

// =====================================================================
// Kernel 1 (one-time ~30us): x[b][t][k] -> g_xt[t][kpair][b][2]
// =====================================================================
__global__ void __launch_bounds__(256) xpose(const float* __restrict__ x)
{
    extern __shared__ float xs[];   // 32 x 513
    const int t   = blockIdx.x;
    const int tid = threadIdx.x;
#pragma unroll
    for (int it = 0; it < 16; it++) {
        int b  = it * 2 + (tid >> 7);
        int k4 = (tid & 127) << 2;
        float4 v = *(const float4*)&x[((size_t)b * SS + t) * II + k4];
        xs[b * 513 + k4 + 0] = v.x;
        xs[b * 513 + k4 + 1] = v.y;
        xs[b * 513 + k4 + 2] = v.z;
        xs[b * 513 + k4 + 3] = v.w;
    }
    __syncthreads();
#pragma unroll
    for (int it = 0; it < 32; it++) {
        int idx = tid + it * 256;      // 8192 = 256 kp x 32 b
        int kp  = idx >> 5;
        int b   = idx & 31;
        float lo = xs[b * 513 + 2 * kp];
        float hi = xs[b * 513 + 2 * kp + 1];
        *(float2*)&g_xt[((size_t)t * 256 + kp) * 64 + b * 2] = make_float2(lo, hi);
    }
}

// =====================================================================
// warp-collective arrive (warp 0 of each CTA). Completer's warp
// broadcasts new window to all 128 mailboxes. Window SS resets state.
// =====================================================================
__device__ __forceinline__ void arrive_warp(unsigned win, int cta, int lane)
{
    unsigned completer = 0;
    if (lane == 0) {
        unsigned old;
        int s = cta & 7;
        asm volatile("atom.acq_rel.gpu.global.add.u32 %0, [%1], %2;"
                     : "=r"(old) : "l"(&g_sub[s * 32]), "r"(1u));
        if (old == win * 16u + 15u) {
            asm volatile("atom.acq_rel.gpu.global.add.u32 %0, [%1], %2;"
                         : "=r"(old) : "l"(&g_top[0]), "r"(1u));
            if (old == win * 8u + 7u) completer = 1u;
        }
    }
    completer = __shfl_sync(0xffffffffu, completer, 0);
    if (completer) {
        unsigned val = (win < (unsigned)SS) ? win + 1u : 0u;
        if (lane == 0 && win == (unsigned)SS) {
#pragma unroll
            for (int i = 0; i < 8; i++) g_sub[i * 32] = 0;
            g_top[0] = 0;
        }
#pragma unroll
        for (int i = 0; i < 4; i++)
            st_rel(&g_mail[(lane + i * 32) * 32], val);
    }
}

// h phase: 16 rows x this warp's 64-k chunk, warp-uniform W (1 wf/LDS)
__device__ __forceinline__ void fma_phase_h(
    const float* __restrict__ Wp, const u64* __restrict__ v2,
    float* __restrict__ sums, int kb)
{
#pragma unroll
    for (int r0 = 0; r0 < 16; r0 += 4) {
        u64 a0[4], a1[4];
#pragma unroll
        for (int rr = 0; rr < 4; rr++) { a0[rr] = 0ull; a1[rr] = 0ull; }
#pragma unroll
        for (int q = 0; q < 16; q++) {
#pragma unroll
            for (int rr = 0; rr < 4; rr++) {
                ulonglong2 wv = *(const ulonglong2*)&Wp[(r0 + rr) * 512 + kb + q * 4];
                a0[rr] = fma2(wv.x, v2[2 * q + 0], a0[rr]);
                a1[rr] = fma2(wv.y, v2[2 * q + 1], a1[rr]);
            }
        }
#pragma unroll
        for (int rr = 0; rr < 4; rr++) {
            float2 f = unpack2(add2(a0[rr], a1[rr]));
            sums[r0 + rr] += f.x + f.y;
        }
    }
}

// x phase over a 32-k half, TWO steps per W load (1 LDS.128 -> 4 fma2)
__device__ __forceinline__ void fma_phase_x2(
    const float* __restrict__ Wp, const u64* __restrict__ xa,
    const u64* __restrict__ xb, float* __restrict__ st,
    float* __restrict__ st1, int kbh)
{
#pragma unroll
    for (int r0 = 0; r0 < 16; r0 += 2) {
        u64 at[2], at1[2], bt[2], bt1[2];
#pragma unroll
        for (int rr = 0; rr < 2; rr++) { at[rr]=0ull; at1[rr]=0ull; bt[rr]=0ull; bt1[rr]=0ull; }
#pragma unroll
        for (int q = 0; q < 8; q++) {
#pragma unroll
            for (int rr = 0; rr < 2; rr++) {
                ulonglong2 wv = *(const ulonglong2*)&Wp[(r0 + rr) * 512 + kbh + q * 4];
                at [rr] = fma2(wv.x, xa[2 * q + 0], at [rr]);
                at1[rr] = fma2(wv.x, xb[2 * q + 0], at1[rr]);
                bt [rr] = fma2(wv.y, xa[2 * q + 1], bt [rr]);
                bt1[rr] = fma2(wv.y, xb[2 * q + 1], bt1[rr]);
            }
        }
#pragma unroll
        for (int rr = 0; rr < 2; rr++) {
            float2 f0 = unpack2(add2(at[rr], bt[rr]));
            float2 f1 = unpack2(add2(at1[rr], bt1[rr]));
            st [r0 + rr] += f0.x + f0.y;
            st1[r0 + rr] += f1.x + f1.y;
        }
    }
}

// =====================================================================
// Kernel 2: fused persistent LSTM. 128 CTAs x 256 thr.
// CTA owns 4 h-idx (16 gate rows); warp owns 64-k chunk; lane = batch.
// Loop processes 2 steps: even step runs one W_ih pass producing
// x-partials for t AND t+1; each step then: mailbox wait -> h load
// (float4) -> h-FMA -> STS -> sync -> warp0 reduce/nonlin/store/arrive.
// =====================================================================
__global__ void __launch_bounds__(256, 1) lstm_rec(
    const float* __restrict__ Wih, const float* __restrict__ Whh,
    const float* __restrict__ bih, const float* __restrict__ bhh,
    const float* __restrict__ h0, const float* __restrict__ c0,
    float* __restrict__ out, int write_hc)
{
    extern __shared__ float sm[];
    float* Wih_s = sm;                 // 16 x 512 = 32KB
    float* Whh_s = sm + 16 * 512;      // 32KB
    float* part  = sm + 32 * 512;      // [16 rows][8 w][32 b] = 16KB

    const int tid  = threadIdx.x;
    const int w    = tid >> 5;
    const int lane = tid & 31;         // lane = batch
    const int cta  = blockIdx.x;
    const int j0   = cta * 4;
    const int kb   = w * 64;           // this warp's k chunk (floats)

    // ---- load W slices (16 rows x 512 each), rows r = type*4 + j ----
#pragma unroll
    for (int s = 0; s < 16; s++) {
        int idx = tid + s * 256;              // 4096 float4 slots
        int mat = idx >> 11;                  // 0 = Wih, 1 = Whh
        int rr  = (idx & 2047) >> 7;
        int k4  = (idx & 127) << 2;
        int g   = (rr >> 2) * 512 + j0 + (rr & 3);
        float* dst = (mat ? Whh_s : Wih_s) + rr * 512 + k4;
        const float* src = (mat ? Whh : Wih) + (size_t)g * 512 + k4;
        *(float4*)dst = *(const float4*)src;
    }

    // ---- warp 0 state: lane = batch; c + biases for j0..j0+3 ----
    float4 creg = make_float4(0.f, 0.f, 0.f, 0.f);
    float4 bias[4];
    if (w == 0) {
        creg = *(const float4*)&c0[(size_t)lane * HH + j0];
        float4 hv = *(const float4*)&h0[(size_t)lane * HH + j0];
        stcg_v4f32(&g_hb[0][(j0 >> 2) * 128 + lane * 4], hv.x, hv.y, hv.z, hv.w);
#pragma unroll
        for (int t4 = 0; t4 < 4; t4++) {
            float4 b1 = *(const float4*)&bih[t4 * 512 + j0];
            float4 b2 = *(const float4*)&bhh[t4 * 512 + j0];
            bias[t4] = make_float4(b1.x + b2.x, b1.y + b2.y, b1.z + b2.z, b1.w + b2.w);
        }
    }
    __syncthreads();
    if (w == 0) arrive_warp(0u, cta, lane);   // window 0: h0 published

    const u64* xt64 = (const u64*)g_xt;
    const unsigned* mybox = &g_mail[cta * 32];

#pragma unroll 1
    for (int t = 0; t < SS; t += 2) {
        float sums_t[16], sums_t1[16];
#pragma unroll
        for (int r = 0; r < 16; r++) { sums_t[r] = 0.f; sums_t1[r] = 0.f; }

        // ---- phase A2: x partials for t and t+1, one W_ih pass ----
#pragma unroll
        for (int hh = 0; hh < 2; hh++) {
            u64 xa[16], xb[16];
#pragma unroll
            for (int i = 0; i < 16; i++) {
                size_t base = (size_t)w * 32 + hh * 16 + i;
                xa[i] = ldcg_u64(&xt64[((size_t)t       * 256 + base) * 32 + lane]);
                xb[i] = ldcg_u64(&xt64[((size_t)(t + 1) * 256 + base) * 32 + lane]);
            }
            fma_phase_x2(Wih_s, xa, xb, sums_t, sums_t1, kb + hh * 32);
        }

        // ============ two recurrence sub-steps ============
#pragma unroll
        for (int sub = 0; sub < 2; sub++) {
            const int tc = t + sub;
            float* sums = sub ? sums_t1 : sums_t;

            // ---- wait: h(tc) published ----
            while (ld_acq(mybox) < (unsigned)(tc + 1)) { }

            // ---- h loads as float4 quads ----
            const ulonglong2* hb128 = (const ulonglong2*)g_hb[tc & 1];
            u64 h2[32];
#pragma unroll
            for (int i = 0; i < 16; i++) {
                ulonglong2 v = ldcg_v2u64(&hb128[(w * 16 + i) * 32 + lane]);
                h2[2 * i + 0] = v.x;
                h2[2 * i + 1] = v.y;
            }

            // ---- h-FMA ----
            fma_phase_h(Whh_s, h2, sums, kb);

#pragma unroll
            for (int r = 0; r < 16; r++)
                part[r * 256 + w * 32 + lane] = sums[r];
            __syncthreads();

            // ---- warp 0: reduce + nonlinearity + stores + arrive ----
            if (w == 0) {
                float gate[4][4];   // [type][j]
#pragma unroll
                for (int t4 = 0; t4 < 4; t4++) {
                    float bv[4] = {bias[t4].x, bias[t4].y, bias[t4].z, bias[t4].w};
#pragma unroll
                    for (int j = 0; j < 4; j++) {
                        int r = t4 * 4 + j;
                        float s = bv[j];
#pragma unroll
                        for (int ww = 0; ww < 8; ww++)
                            s += part[r * 256 + ww * 32 + lane];
                        gate[t4][j] = s;
                    }
                }
                float hv[4], cv[4];
                float cr[4] = {creg.x, creg.y, creg.z, creg.w};
#pragma unroll
                for (int j = 0; j < 4; j++) {
                    float ig = sigmoid_fast(gate[0][j]);
                    float fg = sigmoid_fast(gate[1][j]);
                    float gg = tanh_fast(gate[2][j]);
                    float og = sigmoid_fast(gate[3][j]);
                    float c  = fg * cr[j] + ig * gg;
                    cv[j] = c;
                    hv[j] = og * tanh_fast(c);
                }
                creg = make_float4(cv[0], cv[1], cv[2], cv[3]);

                stcg_v4f32(&g_hb[(tc + 1) & 1][(j0 >> 2) * 128 + lane * 4],
                           hv[0], hv[1], hv[2], hv[3]);
                *(float4*)&out[((size_t)lane * SS + tc) * HH + j0] =
                    make_float4(hv[0], hv[1], hv[2], hv[3]);
                if (tc == SS - 1 && write_hc) {
                    size_t base = (size_t)BB * SS * HH;
                    *(float4*)&out[base + (size_t)lane * HH + j0] =
                        make_float4(hv[0], hv[1], hv[2], hv[3]);
                    *(float4*)&out[base + (size_t)BB * HH + (size_t)lane * HH + j0] =
                        make_float4(cv[0], cv[1], cv[2], cv[3]);
                }
                __syncwarp();
                arrive_warp((unsigned)(tc + 1), cta, lane);
            }
            // warps 1-7 run ahead; part overwrite gated by the mailbox wait.
        }
    }
}

// =====================================================================
extern "C" void kernel_launch(void* const* d_in, const int* in_sizes, int n_in,
                              void* d_out, int out_size)
{
    const float* x   = (const float*)d_in[0];
    const float* Wih = (const float*)d_in[1];
    const float* Whh = (const float*)d_in[2];
    const float* bih = (const float*)d_in[3];
    const float* bhh = (const float*)d_in[4];
    const float* h0  = (const float*)d_in[5];
    const float* c0  = (const float*)d_in[6];
    float* out = (float*)d_out;

    long long need = (long long)BB * SS * HH + 2LL * BB * HH;
    int write_hc = ((long long)out_size >= need) ? 1 : 0;

    int xpose_smem = 32 * 513 * (int)sizeof(float);                  // ~64KB
    int rec_smem   = (32 * 512 + 16 * 256) * (int)sizeof(float);     // 80KB
    cudaFuncSetAttribute(xpose, cudaFuncAttributeMaxDynamicSharedMemorySize, xpose_smem);
    cudaFuncSetAttribute(lstm_rec, cudaFuncAttributeMaxDynamicSharedMemorySize, rec_smem);

    xpose<<<SS, 256, xpose_smem>>>(x);
    lstm_rec<<<128, 256, rec_smem>>>(Wih, Whh, bih, bhh, h0, c0, out, write_hc);
}

// round 10
// speedup vs baseline: 1.0740x; 1.0740x over previous
#include <cuda_runtime.h>
#include <math.h>

#define BB 32
#define SS 1024
#define II 512
#define HH 512
#define GG 2048    // 4*H
#define NPROD 10   // producer warps (= ring slots)
#define NWARP 18   // 10 producers + 8 recurrence

typedef unsigned long long u64;

// ---------------- device scratch ----------------
__device__ float g_xt[(size_t)SS * 256 * 64];   // x transposed: [t][kpair][b][2], 64MB
__device__ float g_hb[2][HH * BB];              // h ping-pong: [kquad][b][4]
__device__ unsigned g_sub[8 * 32];              // barrier: 8 sub-counters (16 CTAs each)
__device__ unsigned g_top[32];                  // top counter (8 subs)
__device__ unsigned g_gen;                      // window counter

__device__ __forceinline__ unsigned ld_acq(const unsigned* p) {
    unsigned v;
    asm volatile("ld.acquire.gpu.u32 %0, [%1];" : "=r"(v) : "l"(p));
    return v;
}
__device__ __forceinline__ unsigned sm_u32(const void* p) {
    unsigned a;
    asm("{ .reg .u64 t; cvta.to.shared.u64 t, %1; cvt.u32.u64 %0, t; }"
        : "=r"(a) : "l"(p));
    return a;
}
__device__ __forceinline__ unsigned ld_acq_sh(unsigned a) {
    unsigned v;
    asm volatile("ld.acquire.cta.shared.u32 %0, [%1];" : "=r"(v) : "r"(a));
    return v;
}
__device__ __forceinline__ void st_rel_sh(unsigned a, unsigned v) {
    asm volatile("st.release.cta.shared.u32 [%0], %1;" :: "r"(a), "r"(v));
}
__device__ __forceinline__ u64 fma2(u64 a, u64 b, u64 c) {
    u64 d;
    asm("fma.rn.f32x2 %0, %1, %2, %3;" : "=l"(d) : "l"(a), "l"(b), "l"(c));
    return d;
}
__device__ __forceinline__ u64 add2(u64 a, u64 b) {
    u64 d;
    asm("add.rn.f32x2 %0, %1, %2;" : "=l"(d) : "l"(a), "l"(b));
    return d;
}
__device__ __forceinline__ float2 unpack2(u64 v) {
    unsigned lo, hi;
    asm("mov.b64 {%0, %1}, %2;" : "=r"(lo), "=r"(hi) : "l"(v));
    return make_float2(__uint_as_float(lo), __uint_as_float(hi));
}
__device__ __forceinline__ u64 ldcg_u64(const u64* p) {
    u64 v;
    asm volatile("ld.global.cg.u64 %0, [%1];" : "=l"(v) : "l"(p));
    return v;
}
__device__ __forceinline__ ulonglong2 ldcg_v2u64(const void* p) {
    ulonglong2 v;
    asm volatile("ld.global.cg.v2.u64 {%0, %1}, [%2];"
                 : "=l"(v.x), "=l"(v.y) : "l"(p));
    return v;
}
__device__ __forceinline__ void stcg_v4f32(float* p, float a, float b, float c, float d) {
    asm volatile("st.global.cg.v4.f32 [%0], {%1, %2, %3, %4};"
                 :: "l"(p), "f"(a), "f"(b), "f"(c), "f"(d));
}
__device__ __forceinline__ float sigmoid_fast(float x) {
    return __fdividef(1.f, 1.f + __expf(-x));
}
__device__ __forceinline__ float tanh_fast(float x) {
    float e2 = __expf(2.f * fabsf(x));
    float r  = 1.f - __fdividef(2.f, e2 + 1.f);
    return copysignf(r, x);
}

// =====================================================================
// Kernel 1 (one-time ~30us): x[b][t][k] -> g_xt[t][kpair][b][2]
// =====================================================================
__global__ void __launch_bounds__(256) xpose(const float* __restrict__ x)
{
    extern __shared__ float xs[];   // 32 x 513
    const int t   = blockIdx.x;
    const int tid = threadIdx.x;
#pragma unroll
    for (int it = 0; it < 16; it++) {
        int b  = it * 2 + (tid >> 7);
        int k4 = (tid & 127) << 2;
        float4 v = *(const float4*)&x[((size_t)b * SS + t) * II + k4];
        xs[b * 513 + k4 + 0] = v.x;
        xs[b * 513 + k4 + 1] = v.y;
        xs[b * 513 + k4 + 2] = v.z;
        xs[b * 513 + k4 + 3] = v.w;
    }
    __syncthreads();
#pragma unroll
    for (int it = 0; it < 32; it++) {
        int idx = tid + it * 256;      // 8192 = 256 kp x 32 b
        int kp  = idx >> 5;
        int b   = idx & 31;
        float lo = xs[b * 513 + 2 * kp];
        float hi = xs[b * 513 + 2 * kp + 1];
        *(float2*)&g_xt[((size_t)t * 256 + kp) * 64 + b * 2] = make_float2(lo, hi);
    }
}

// =====================================================================
// global barrier arrive (lane0 of reduce warp). Window SS resets state.
// =====================================================================
__device__ __forceinline__ void arrive(unsigned win, int cta)
{
    unsigned old;
    int sb = cta & 7;
    asm volatile("atom.acq_rel.gpu.global.add.u32 %0, [%1], %2;"
                 : "=r"(old) : "l"(&g_sub[sb * 32]), "r"(1u));
    if (old == win * 16u + 15u) {
        asm volatile("atom.acq_rel.gpu.global.add.u32 %0, [%1], %2;"
                     : "=r"(old) : "l"(&g_top[0]), "r"(1u));
        if (old == win * 8u + 7u) {
            if (win == (unsigned)SS) {
#pragma unroll
                for (int i = 0; i < 8; i++) g_sub[i * 32] = 0;
                g_top[0] = 0;
                asm volatile("atom.release.gpu.global.exch.b32 %0, [%1], %2;"
                             : "=r"(old) : "l"(&g_gen), "r"(0u));
            } else {
                asm volatile("atom.release.gpu.global.exch.b32 %0, [%1], %2;"
                             : "=r"(old) : "l"(&g_gen), "r"(win + 1u));
            }
        }
    }
}

// 16 rows x 32-k chunk; warp-uniform W (1 wf per LDS.128); 2 acc banks
__device__ __forceinline__ void fma_chunk32(
    const float* __restrict__ Wp, const u64* __restrict__ v2,
    float* __restrict__ sums, int kb)
{
#pragma unroll
    for (int r0 = 0; r0 < 16; r0 += 4) {
        u64 a0[4], a1[4];
#pragma unroll
        for (int rr = 0; rr < 4; rr++) { a0[rr] = 0ull; a1[rr] = 0ull; }
#pragma unroll
        for (int q = 0; q < 8; q++) {
#pragma unroll
            for (int rr = 0; rr < 4; rr++) {
                ulonglong2 wv = *(const ulonglong2*)&Wp[(r0 + rr) * 512 + kb + q * 4];
                a0[rr] = fma2(wv.x, v2[2 * q + 0], a0[rr]);
                a1[rr] = fma2(wv.y, v2[2 * q + 1], a1[rr]);
            }
        }
#pragma unroll
        for (int rr = 0; rr < 4; rr++) {
            float2 f = unpack2(add2(a0[rr], a1[rr]));
            sums[r0 + rr] += f.x + f.y;
        }
    }
}

// =====================================================================
// Kernel 2: warp-specialized persistent LSTM. 128 CTAs x 576 threads.
// CTA owns 4 h-idx (16 gate rows). Warps 0-9: x-gate producers filling
// a 10-slot smem ring (each owns its slot; acquire/release smem flags).
// Warps 10-17: recurrence (R6 structure); warp 10 reduces using the
// ring tile instead of recomputing the x contribution.
// =====================================================================
__global__ void __launch_bounds__(576, 1) lstm_rec(
    const float* __restrict__ Wih, const float* __restrict__ Whh,
    const float* __restrict__ bih, const float* __restrict__ bhh,
    const float* __restrict__ h0, const float* __restrict__ c0,
    float* __restrict__ out, int write_hc)
{
    extern __shared__ float sm[];
    float* Wih_s  = sm;                   // 16 x 512 = 32KB
    float* Whh_s  = sm + 8192;            // 32KB
    float* part   = sm + 16384;           // [16 rows][8 rw][32 b] = 16KB
    float* ring   = sm + 20480;           // [NPROD slots][16 rows][32 b] = 20KB
    float* bias_s = sm + 20480 + NPROD * 512;            // 16 floats
    unsigned* rdy = (unsigned*)(bias_s + 16);            // NPROD flags
    unsigned* frd = rdy + 32;                            // NPROD flags

    const int tid  = threadIdx.x;
    const int w    = tid >> 5;
    const int lane = tid & 31;          // lane = batch
    const int cta  = blockIdx.x;
    const int j0   = cta * 4;

    // ---- load W slices (16 rows x 512 each), rows r = type*4 + j ----
#pragma unroll
    for (int s = 0; s < 8; s++) {
        int idx = tid + s * 576;              // 4096 float4 slots (+ tail guard)
        if (idx < 4096) {
            int mat = idx >> 11;              // 0 = Wih, 1 = Whh
            int rr  = (idx & 2047) >> 7;
            int k4  = (idx & 127) << 2;
            int g   = (rr >> 2) * 512 + j0 + (rr & 3);
            float* dst = (mat ? Whh_s : Wih_s) + rr * 512 + k4;
            const float* src = (mat ? Whh : Wih) + (size_t)g * 512 + k4;
            *(float4*)dst = *(const float4*)src;
        }
    }
    // flags + bias
    if (tid < NPROD) { rdy[tid] = 0u; frd[tid] = 0u; }
    if (tid >= 32 && tid < 48) {
        int r = tid - 32;
        int g = (r >> 2) * 512 + j0 + (r & 3);
        bias_s[r] = bih[g] + bhh[g];
    }

    // ---- warp 10 (reduce warp) state: lane = batch; c for j0..j0+3 ----
    float4 creg = make_float4(0.f, 0.f, 0.f, 0.f);
    if (w == NPROD) {
        creg = *(const float4*)&c0[(size_t)lane * HH + j0];
        float4 hv = *(const float4*)&h0[(size_t)lane * HH + j0];
        stcg_v4f32(&g_hb[0][cta * 128 + lane * 4], hv.x, hv.y, hv.z, hv.w);
    }
    __syncthreads();
    if (w == NPROD && lane == 0) arrive(0u, cta);   // window 0: h0 published

    const u64* xt64 = (const u64*)g_xt;

    if (w < NPROD) {
        // ================= producer warp w: x-gate tiles =================
        const unsigned fa = sm_u32(&frd[w]);
        const unsigned ra = sm_u32(&rdy[w]);
        float* myring = &ring[w * 512];
        int e = 0;
#pragma unroll 1
        for (int t = w; t < SS; t += NPROD, e++) {
            if (e > 0) {
                unsigned v = ld_acq_sh(fa);
                while (v < (unsigned)e) { __nanosleep(64); v = ld_acq_sh(fa); }
            }
            float sums[16];
#pragma unroll
            for (int r = 0; r < 16; r++) sums[r] = 0.f;
#pragma unroll 1
            for (int kc = 0; kc < 16; kc++) {
                u64 x2[16];
#pragma unroll
                for (int i = 0; i < 16; i++)
                    x2[i] = ldcg_u64(&xt64[((size_t)t * 256 + kc * 16 + i) * 32 + lane]);
                fma_chunk32(Wih_s, x2, sums, kc * 32);
            }
#pragma unroll
            for (int r = 0; r < 16; r++)
                myring[r * 32 + lane] = sums[r];
            __syncwarp();
            if (lane == 0) st_rel_sh(ra, (unsigned)(e + 1));
        }
    } else {
        // ================= recurrence warps (8) =================
        const int rw = w - NPROD;       // 0..7
        const int kb = rw * 64;
        int slot = 0, ep = 0;           // ring cursor (reduce warp)

#pragma unroll 1
        for (int t = 0; t < SS; t++) {
            // ---- wait: h(t) published ----
            while (ld_acq(&g_gen) < (unsigned)(t + 1)) { }

            // ---- h loads: 16 x LDG.128 ----
            const ulonglong2* hb128 = (const ulonglong2*)g_hb[t & 1];
            u64 h2[32];
#pragma unroll
            for (int i = 0; i < 16; i++) {
                ulonglong2 v = ldcg_v2u64(&hb128[(rw * 16 + i) * 32 + lane]);
                h2[2 * i + 0] = v.x;
                h2[2 * i + 1] = v.y;
            }

            float sums[16];
#pragma unroll
            for (int r = 0; r < 16; r++) sums[r] = 0.f;
            fma_chunk32(Whh_s, h2,      sums, kb);
            fma_chunk32(Whh_s, h2 + 16, sums, kb + 32);

#pragma unroll
            for (int r = 0; r < 16; r++)
                part[r * 256 + rw * 32 + lane] = sums[r];
            asm volatile("bar.sync 1, 256;" ::: "memory");

            // ---- reduce warp: gates = bias + ring + sum(part) ----
            if (rw == 0) {
                // wait for this step's x tile
                const unsigned ra = sm_u32(&rdy[slot]);
                unsigned v = ld_acq_sh(ra);
                while (v < (unsigned)(ep + 1)) { __nanosleep(32); v = ld_acq_sh(ra); }

                const float* tile = &ring[slot * 512];
                float gate[4][4];   // [type][j]
#pragma unroll
                for (int t4 = 0; t4 < 4; t4++) {
#pragma unroll
                    for (int j = 0; j < 4; j++) {
                        int r = t4 * 4 + j;
                        float s = bias_s[r] + tile[r * 32 + lane];
#pragma unroll
                        for (int ww = 0; ww < 8; ww++)
                            s += part[r * 256 + ww * 32 + lane];
                        gate[t4][j] = s;
                    }
                }
                float hv[4], cv[4];
                float cr[4] = {creg.x, creg.y, creg.z, creg.w};
#pragma unroll
                for (int j = 0; j < 4; j++) {
                    float ig = sigmoid_fast(gate[0][j]);
                    float fg = sigmoid_fast(gate[1][j]);
                    float gg = tanh_fast(gate[2][j]);
                    float og = sigmoid_fast(gate[3][j]);
                    float c  = fg * cr[j] + ig * gg;
                    cv[j] = c;
                    hv[j] = og * tanh_fast(c);
                }
                creg = make_float4(cv[0], cv[1], cv[2], cv[3]);

                stcg_v4f32(&g_hb[(t + 1) & 1][cta * 128 + lane * 4],
                           hv[0], hv[1], hv[2], hv[3]);
                *(float4*)&out[((size_t)lane * SS + t) * HH + j0] =
                    make_float4(hv[0], hv[1], hv[2], hv[3]);
                if (t == SS - 1 && write_hc) {
                    size_t base = (size_t)BB * SS * HH;
                    *(float4*)&out[base + (size_t)lane * HH + j0] =
                        make_float4(hv[0], hv[1], hv[2], hv[3]);
                    *(float4*)&out[base + (size_t)BB * HH + (size_t)lane * HH + j0] =
                        make_float4(cv[0], cv[1], cv[2], cv[3]);
                }
                __syncwarp();
                if (lane == 0) {
                    st_rel_sh(sm_u32(&frd[slot]), (unsigned)(ep + 1));
                    arrive((unsigned)(t + 1), cta);
                }
                if (++slot == NPROD) { slot = 0; ep++; }
            }
            // warps rw>0 run ahead; part overwrite at t+1 is gated by the
            // g_gen wait (needs our reduce warp's arrive).
        }
    }
}

// =====================================================================
extern "C" void kernel_launch(void* const* d_in, const int* in_sizes, int n_in,
                              void* d_out, int out_size)
{
    const float* x   = (const float*)d_in[0];
    const float* Wih = (const float*)d_in[1];
    const float* Whh = (const float*)d_in[2];
    const float* bih = (const float*)d_in[3];
    const float* bhh = (const float*)d_in[4];
    const float* h0  = (const float*)d_in[5];
    const float* c0  = (const float*)d_in[6];
    float* out = (float*)d_out;

    long long need = (long long)BB * SS * HH + 2LL * BB * HH;
    int write_hc = ((long long)out_size >= need) ? 1 : 0;

    int xpose_smem = 32 * 513 * (int)sizeof(float);   // ~64KB
    int rec_smem   = (20480 + NPROD * 512 + 16 + 64) * (int)sizeof(float) + 256;
    cudaFuncSetAttribute(xpose, cudaFuncAttributeMaxDynamicSharedMemorySize, xpose_smem);
    cudaFuncSetAttribute(lstm_rec, cudaFuncAttributeMaxDynamicSharedMemorySize, rec_smem);

    xpose<<<SS, 256, xpose_smem>>>(x);
    lstm_rec<<<128, 576, rec_smem>>>(Wih, Whh, bih, bhh, h0, c0, out, write_hc);
}